// round 1
// baseline (speedup 1.0000x reference)
#include <cuda_runtime.h>
#include <math.h>

#define Bb 256
#define Tt 256
#define Dd 64
#define Hh 512

typedef unsigned long long ull;

// Scratch buffers (device globals: allocation-free rule). 134 MB each.
__device__ float g_xp[(size_t)Bb * Tt * Hh];  // input projections for current layer
__device__ float g_h [(size_t)Bb * Tt * Hh];  // hidden-state sequence for current layer

// ---------------- packed dual-fp32 helpers (sm_100+ f32x2 pipe) ----------------
__device__ __forceinline__ ull fma2(ull a, ull b, ull c) {
    ull d;
    asm("fma.rn.f32x2 %0, %1, %2, %3;" : "=l"(d) : "l"(a), "l"(b), "l"(c));
    return d;
}
__device__ __forceinline__ ull dup2(float x) {
    ull d;
    asm("mov.b64 %0, {%1, %2};" : "=l"(d) : "f"(x), "f"(x));
    return d;
}
__device__ __forceinline__ float2 unpack2(ull v) {
    float2 r;
    asm("mov.b64 {%0, %1}, %2;" : "=f"(r.x), "=f"(r.y) : "l"(v));
    return r;
}

// ---------------------------------------------------------------------------
// Projection GEMM: out[M,Hh] = A[M,K] @ W[K,Hh] + bias    (M = Bb*Tt = 65536)
// Tile 64x64, BK=16, 256 threads, per-thread 4x4 via f32x2.
// ---------------------------------------------------------------------------
template <int K>
__global__ __launch_bounds__(256) void proj_kernel(
    const float* __restrict__ A, const float* __restrict__ W,
    const float* __restrict__ bias, float* __restrict__ out)
{
    __shared__ float sA[16 * 68];   // A^T tile: sA[kk*68 + m]
    __shared__ float sB[16 * 68];   // W tile:   sB[kk*68 + n]

    const int n0 = blockIdx.x * 64;
    const int m0 = blockIdx.y * 64;
    const int tid = threadIdx.x;
    const int tx = tid & 15;        // 16 col groups of 4
    const int ty = tid >> 4;        // 16 row groups of 4

    const int arow = tid >> 2, ac4 = tid & 3;    // A loader: 64 rows x 4 float4
    const int bk = tid >> 4, bc4 = tid & 15;     // B loader: 16 k x 16 float4

    ull acc[4][2];
#pragma unroll
    for (int i = 0; i < 4; i++) { acc[i][0] = 0ull; acc[i][1] = 0ull; }

    for (int k0 = 0; k0 < K; k0 += 16) {
        float4 va = *(const float4*)&A[(size_t)(m0 + arow) * K + k0 + ac4 * 4];
        float4 vb = *(const float4*)&W[(size_t)(k0 + bk) * Hh + n0 + bc4 * 4];
        sA[(ac4 * 4 + 0) * 68 + arow] = va.x;
        sA[(ac4 * 4 + 1) * 68 + arow] = va.y;
        sA[(ac4 * 4 + 2) * 68 + arow] = va.z;
        sA[(ac4 * 4 + 3) * 68 + arow] = va.w;
        *(float4*)&sB[bk * 68 + bc4 * 4] = vb;
        __syncthreads();
#pragma unroll
        for (int kk = 0; kk < 16; kk++) {
            float4 a = *(const float4*)&sA[kk * 68 + ty * 4];
            ulonglong2 b = *(const ulonglong2*)&sB[kk * 68 + tx * 4];
            ull a0 = dup2(a.x), a1 = dup2(a.y), a2 = dup2(a.z), a3 = dup2(a.w);
            acc[0][0] = fma2(a0, b.x, acc[0][0]); acc[0][1] = fma2(a0, b.y, acc[0][1]);
            acc[1][0] = fma2(a1, b.x, acc[1][0]); acc[1][1] = fma2(a1, b.y, acc[1][1]);
            acc[2][0] = fma2(a2, b.x, acc[2][0]); acc[2][1] = fma2(a2, b.y, acc[2][1]);
            acc[3][0] = fma2(a3, b.x, acc[3][0]); acc[3][1] = fma2(a3, b.y, acc[3][1]);
        }
        __syncthreads();
    }

    float4 bi = *(const float4*)&bias[n0 + tx * 4];
#pragma unroll
    for (int i = 0; i < 4; i++) {
        float2 u0 = unpack2(acc[i][0]);
        float2 u1 = unpack2(acc[i][1]);
        float4 o;
        o.x = u0.x + bi.x; o.y = u0.y + bi.y; o.z = u1.x + bi.z; o.w = u1.y + bi.w;
        *(float4*)&out[(size_t)(m0 + ty * 4 + i) * Hh + n0 + tx * 4] = o;
    }
}

// ---------------------------------------------------------------------------
// Recurrence step t=0:  h[:,0,:] = tanh(xp[:,0,:])
// ---------------------------------------------------------------------------
__global__ void step0_kernel(const float* __restrict__ xp, float* __restrict__ h)
{
    int idx = blockIdx.x * blockDim.x + threadIdx.x;   // over Bb*Hh
    int b = idx >> 9;          // /512
    int j = idx & (Hh - 1);
    size_t off = ((size_t)b * Tt) * Hh + j;
    h[off] = tanhf(xp[off]);
}

// ---------------------------------------------------------------------------
// Recurrence step t>0: h[:,t,:] = tanh(xp[:,t,:] + h[:,t-1,:] @ Wh)
// Grid: (8 col-tiles of 64) x (16 batch-tiles of 16).  128 threads/CTA.
// SMEM: full Wh column slice [512x64] + transposed h tile [512x18pad].
// ---------------------------------------------------------------------------
#define STEP_SMEM ((512 * 64 + 512 * 18) * 4)

extern __shared__ float s_mem[];

__global__ __launch_bounds__(128, 1) void step_kernel(
    const float* __restrict__ xp, const float* __restrict__ Wh,
    float* __restrict__ h, int t)
{
    float* sW = s_mem;               // [512][64]
    float* sH = s_mem + 512 * 64;    // [512][18], 16 rows used

    const int n0 = blockIdx.x * 64;
    const int b0 = blockIdx.y * 16;
    const int tid = threadIdx.x;

    // Stage Wh[:, n0:n0+64]  (128 KB)
    for (int i = tid; i < 512 * 16; i += 128) {
        int k = i >> 4, c4 = i & 15;
        float4 v = *(const float4*)&Wh[(size_t)k * Hh + n0 + c4 * 4];
        *(float4*)&sW[k * 64 + c4 * 4] = v;
    }
    // Stage h_prev[b0:b0+16, :] transposed (32 KB logical)
    for (int i = tid; i < 16 * 128; i += 128) {
        int r = i >> 7, k4 = i & 127;
        float4 v = *(const float4*)&h[(((size_t)(b0 + r) * Tt) + (t - 1)) * Hh + k4 * 4];
        sH[(k4 * 4 + 0) * 18 + r] = v.x;
        sH[(k4 * 4 + 1) * 18 + r] = v.y;
        sH[(k4 * 4 + 2) * 18 + r] = v.z;
        sH[(k4 * 4 + 3) * 18 + r] = v.w;
    }
    __syncthreads();

    const int tx = tid & 15;   // 16 col groups of 4
    const int ty = tid >> 4;   // 8 row groups of 2
    const int r0 = ty * 2;
    const int c0 = tx * 4;

    ull acc00 = 0ull, acc01 = 0ull, acc10 = 0ull, acc11 = 0ull;
#pragma unroll 8
    for (int k = 0; k < 512; k++) {
        float2 hv = *(const float2*)&sH[k * 18 + r0];       // r0 even -> 8B aligned
        ull a0 = dup2(hv.x), a1 = dup2(hv.y);
        ulonglong2 bv = *(const ulonglong2*)&sW[k * 64 + c0];
        acc00 = fma2(a0, bv.x, acc00);
        acc01 = fma2(a0, bv.y, acc01);
        acc10 = fma2(a1, bv.x, acc10);
        acc11 = fma2(a1, bv.y, acc11);
    }

    size_t base0 = (((size_t)(b0 + r0) * Tt) + t) * Hh + n0 + c0;
    size_t base1 = (((size_t)(b0 + r0 + 1) * Tt) + t) * Hh + n0 + c0;
    float4 xv0 = *(const float4*)&xp[base0];
    float4 xv1 = *(const float4*)&xp[base1];
    float2 u;
    float4 o;
    u = unpack2(acc00); o.x = tanhf(u.x + xv0.x); o.y = tanhf(u.y + xv0.y);
    u = unpack2(acc01); o.z = tanhf(u.x + xv0.z); o.w = tanhf(u.y + xv0.w);
    *(float4*)&h[base0] = o;
    u = unpack2(acc10); o.x = tanhf(u.x + xv1.x); o.y = tanhf(u.y + xv1.y);
    u = unpack2(acc11); o.z = tanhf(u.x + xv1.z); o.w = tanhf(u.y + xv1.w);
    *(float4*)&h[base1] = o;
}

// ---------------------------------------------------------------------------
// Final: out[b] = h[b, T-1, :] @ Wf + bf
// ---------------------------------------------------------------------------
__global__ void final_kernel(const float* __restrict__ h, const float* __restrict__ Wf,
                             const float* __restrict__ bf, float* __restrict__ out)
{
    int b = blockIdx.x;
    const float* row = h + ((size_t)b * Tt + (Tt - 1)) * Hh;
    float s = 0.f;
    for (int j = threadIdx.x; j < Hh; j += 128) s += row[j] * Wf[j];
#pragma unroll
    for (int o = 16; o > 0; o >>= 1) s += __shfl_down_sync(0xffffffffu, s, o);
    __shared__ float ws[4];
    if ((threadIdx.x & 31) == 0) ws[threadIdx.x >> 5] = s;
    __syncthreads();
    if (threadIdx.x == 0) out[b] = ws[0] + ws[1] + ws[2] + ws[3] + bf[0];
}

// ---------------------------------------------------------------------------
extern "C" void kernel_launch(void* const* d_in, const int* in_sizes, int n_in,
                              void* d_out, int out_size)
{
    const float* x   = (const float*)d_in[0];
    const float* Wx0 = (const float*)d_in[1];
    const float* Wh0 = (const float*)d_in[2];
    const float* b0  = (const float*)d_in[3];
    const float* Wx1 = (const float*)d_in[4];
    const float* Wh1 = (const float*)d_in[5];
    const float* b1  = (const float*)d_in[6];
    const float* Wx2 = (const float*)d_in[7];
    const float* Wh2 = (const float*)d_in[8];
    const float* b2  = (const float*)d_in[9];
    const float* Wf  = (const float*)d_in[10];
    const float* bf  = (const float*)d_in[11];
    float* out = (float*)d_out;

    void* p;
    cudaGetSymbolAddress(&p, g_xp);
    float* xp = (float*)p;
    cudaGetSymbolAddress(&p, g_h);
    float* hb = (float*)p;

    cudaFuncSetAttribute(step_kernel, cudaFuncAttributeMaxDynamicSharedMemorySize, STEP_SMEM);

    dim3 pgrid(Hh / 64, (Bb * Tt) / 64);   // (8, 1024)
    dim3 sgrid(Hh / 64, Bb / 16);          // (8, 16)

    // ---- layer 0 ----
    proj_kernel<Dd><<<pgrid, 256>>>(x, Wx0, b0, xp);
    step0_kernel<<<(Bb * Hh) / 256, 256>>>(xp, hb);
    for (int t = 1; t < Tt; t++)
        step_kernel<<<sgrid, 128, STEP_SMEM>>>(xp, Wh0, hb, t);

    // ---- layer 1 ----
    proj_kernel<Hh><<<pgrid, 256>>>(hb, Wx1, b1, xp);
    step0_kernel<<<(Bb * Hh) / 256, 256>>>(xp, hb);
    for (int t = 1; t < Tt; t++)
        step_kernel<<<sgrid, 128, STEP_SMEM>>>(xp, Wh1, hb, t);

    // ---- layer 2 ----
    proj_kernel<Hh><<<pgrid, 256>>>(hb, Wx2, b2, xp);
    step0_kernel<<<(Bb * Hh) / 256, 256>>>(xp, hb);
    for (int t = 1; t < Tt; t++)
        step_kernel<<<sgrid, 128, STEP_SMEM>>>(xp, Wh2, hb, t);

    // ---- head ----
    final_kernel<<<Bb, 128>>>(hb, Wf, bf, out);
}

// round 2
// speedup vs baseline: 1.7224x; 1.7224x over previous
#include <cuda_runtime.h>
#include <math.h>

#define Bb 256
#define Tt 256
#define Dd 64
#define Hh 512

typedef unsigned long long ull;

// Scratch (device globals: allocation-free rule).
__device__ float g_xp[(size_t)Bb * Tt * Hh];
__device__ float g_h [(size_t)Bb * Tt * Hh];
__device__ int   g_bar[3 * 16];          // per (layer, batch-group) arrival counters

// ---------------- packed dual-fp32 helpers (sm_100+ f32x2) ----------------
__device__ __forceinline__ ull fma2(ull a, ull b, ull c) {
    ull d;
    asm("fma.rn.f32x2 %0, %1, %2, %3;" : "=l"(d) : "l"(a), "l"(b), "l"(c));
    return d;
}
__device__ __forceinline__ ull dup2(float x) {
    ull d;
    asm("mov.b64 %0, {%1, %2};" : "=l"(d) : "f"(x), "f"(x));
    return d;
}
__device__ __forceinline__ float2 unpack2(ull v) {
    float2 r;
    asm("mov.b64 {%0, %1}, %2;" : "=f"(r.x), "=f"(r.y) : "l"(v));
    return r;
}

__global__ void zero_bar_kernel() {
    if (threadIdx.x < 48) g_bar[threadIdx.x] = 0;
}

// ---------------------------------------------------------------------------
// Projection GEMM: out[M,Hh] = A[M,K] @ W[K,Hh] + bias    (M = Bb*Tt)
// ---------------------------------------------------------------------------
template <int K>
__global__ __launch_bounds__(256) void proj_kernel(
    const float* __restrict__ A, const float* __restrict__ W,
    const float* __restrict__ bias, float* __restrict__ out)
{
    __shared__ float sA[16 * 68];
    __shared__ float sB[16 * 68];

    const int n0 = blockIdx.x * 64;
    const int m0 = blockIdx.y * 64;
    const int tid = threadIdx.x;
    const int tx = tid & 15;
    const int ty = tid >> 4;

    const int arow = tid >> 2, ac4 = tid & 3;
    const int bk = tid >> 4, bc4 = tid & 15;

    ull acc[4][2];
#pragma unroll
    for (int i = 0; i < 4; i++) { acc[i][0] = 0ull; acc[i][1] = 0ull; }

    for (int k0 = 0; k0 < K; k0 += 16) {
        float4 va = *(const float4*)&A[(size_t)(m0 + arow) * K + k0 + ac4 * 4];
        float4 vb = *(const float4*)&W[(size_t)(k0 + bk) * Hh + n0 + bc4 * 4];
        sA[(ac4 * 4 + 0) * 68 + arow] = va.x;
        sA[(ac4 * 4 + 1) * 68 + arow] = va.y;
        sA[(ac4 * 4 + 2) * 68 + arow] = va.z;
        sA[(ac4 * 4 + 3) * 68 + arow] = va.w;
        *(float4*)&sB[bk * 68 + bc4 * 4] = vb;
        __syncthreads();
#pragma unroll
        for (int kk = 0; kk < 16; kk++) {
            float4 a = *(const float4*)&sA[kk * 68 + ty * 4];
            ulonglong2 b = *(const ulonglong2*)&sB[kk * 68 + tx * 4];
            ull a0 = dup2(a.x), a1 = dup2(a.y), a2 = dup2(a.z), a3 = dup2(a.w);
            acc[0][0] = fma2(a0, b.x, acc[0][0]); acc[0][1] = fma2(a0, b.y, acc[0][1]);
            acc[1][0] = fma2(a1, b.x, acc[1][0]); acc[1][1] = fma2(a1, b.y, acc[1][1]);
            acc[2][0] = fma2(a2, b.x, acc[2][0]); acc[2][1] = fma2(a2, b.y, acc[2][1]);
            acc[3][0] = fma2(a3, b.x, acc[3][0]); acc[3][1] = fma2(a3, b.y, acc[3][1]);
        }
        __syncthreads();
    }

    float4 bi = *(const float4*)&bias[n0 + tx * 4];
#pragma unroll
    for (int i = 0; i < 4; i++) {
        float2 u0 = unpack2(acc[i][0]);
        float2 u1 = unpack2(acc[i][1]);
        float4 o;
        o.x = u0.x + bi.x; o.y = u0.y + bi.y; o.z = u1.x + bi.z; o.w = u1.y + bi.w;
        *(float4*)&out[(size_t)(m0 + ty * 4 + i) * Hh + n0 + tx * 4] = o;
    }
}

// ---------------------------------------------------------------------------
// Persistent layer kernel: full recurrence for one layer.
// Grid (8 col-tiles x 16 batch-groups) = 128 CTAs, 256 threads each.
// Wh column slice [512x64] resident in SMEM across all 255 steps.
// Split-k by warp: warp w handles k in [w*64, w*64+64) of the whole
// 16x64 tile (thread tile 4 batch x 8 cols), then smem reduction.
// Cross-CTA sync: per-group monotonic arrival counter (8 CTAs/group).
// ---------------------------------------------------------------------------
#define SH_STR   513                         // h tile row stride (pad: conflict-free)
#define RED_STR  66                          // reduction row stride
#define SW_FLOATS (512 * 64)
#define AUX_FLOATS (8 * 16 * RED_STR)        // 8448 >= 16*SH_STR=8208
#define LAYER_SMEM ((SW_FLOATS + AUX_FLOATS) * 4)

extern __shared__ float s_mem[];

__global__ __launch_bounds__(256, 1) void layer_kernel(
    const float* __restrict__ xp, const float* __restrict__ Wh,
    float* __restrict__ h, int* __restrict__ bar, int layer)
{
    float* sW   = s_mem;                 // [512][64]
    float* sAux = s_mem + SW_FLOATS;     // h tile [16][SH_STR]  /  red [8][16][RED_STR]

    const int n0 = blockIdx.x * 64;
    const int b0 = blockIdx.y * 16;
    int* cnt = &bar[layer * 16 + blockIdx.y];

    const int tid  = threadIdx.x;
    const int w    = tid >> 5;           // warp id -> k chunk
    const int lane = tid & 31;
    const int rg   = lane >> 3;          // row group (4 rows)
    const int cg   = lane & 7;           // col group (cols cg*4..+3 and 32+cg*4..+3)
    const int kbase = w * 64;
    const int tx = tid & 15;             // output col group of 4
    const int ty = tid >> 4;             // output batch row

    // ---- stage Wh[:, n0:n0+64] once ----
    for (int i = tid; i < 512 * 16; i += 256) {
        int k = i >> 4, c4 = i & 15;
        float4 v = *(const float4*)&Wh[(size_t)k * Hh + n0 + c4 * 4];
        *(float4*)&sW[k * 64 + c4 * 4] = v;
    }

    // ---- t = 0: h0 = tanh(xp0) ----
    {
        size_t base = ((size_t)(b0 + ty) * Tt) * Hh + n0 + tx * 4;
        float4 xv = *(const float4*)&xp[base];
        float4 o;
        o.x = tanhf(xv.x); o.y = tanhf(xv.y); o.z = tanhf(xv.z); o.w = tanhf(xv.w);
        *(float4*)&h[base] = o;
        __threadfence();
        __syncthreads();
        if (tid == 0) atomicAdd(cnt, 1);
    }

    for (int t = 1; t < Tt; t++) {
        // ---- wait until all 8 producers of this batch group wrote h_{t-1} ----
        if (tid == 0) {
            while (*(volatile int*)cnt < 8 * t) { }
        }
        __syncthreads();
        __threadfence();

        // ---- stage h_{t-1}[b0..b0+15, :] into sAux ([16][SH_STR]) ----
        float* sH = sAux;
#pragma unroll
        for (int j = 0; j < 8; j++) {
            int idx = tid + j * 256;
            int b = idx >> 7, k4 = idx & 127;
            float4 v = *(const float4*)&h[(((size_t)(b0 + b) * Tt) + (t - 1)) * Hh + k4 * 4];
            float* d = &sH[b * SH_STR + k4 * 4];
            d[0] = v.x; d[1] = v.y; d[2] = v.z; d[3] = v.w;
        }
        __syncthreads();

        // ---- split-k compute: warp w does k in [kbase, kbase+64) ----
        ull acc[4][4];
#pragma unroll
        for (int i = 0; i < 4; i++)
#pragma unroll
            for (int j = 0; j < 4; j++) acc[i][j] = 0ull;

        const float* hp = &sH[(rg * 4) * SH_STR + kbase];
        const float* wp = &sW[kbase * 64];
#pragma unroll 2
        for (int kk = 0; kk < 64; kk++) {
            ull a0 = dup2(hp[kk]);
            ull a1 = dup2(hp[SH_STR + kk]);
            ull a2 = dup2(hp[2 * SH_STR + kk]);
            ull a3 = dup2(hp[3 * SH_STR + kk]);
            ulonglong2 wlo = *(const ulonglong2*)&wp[kk * 64 + cg * 4];
            ulonglong2 whi = *(const ulonglong2*)&wp[kk * 64 + 32 + cg * 4];
            acc[0][0] = fma2(a0, wlo.x, acc[0][0]); acc[0][1] = fma2(a0, wlo.y, acc[0][1]);
            acc[0][2] = fma2(a0, whi.x, acc[0][2]); acc[0][3] = fma2(a0, whi.y, acc[0][3]);
            acc[1][0] = fma2(a1, wlo.x, acc[1][0]); acc[1][1] = fma2(a1, wlo.y, acc[1][1]);
            acc[1][2] = fma2(a1, whi.x, acc[1][2]); acc[1][3] = fma2(a1, whi.y, acc[1][3]);
            acc[2][0] = fma2(a2, wlo.x, acc[2][0]); acc[2][1] = fma2(a2, wlo.y, acc[2][1]);
            acc[2][2] = fma2(a2, whi.x, acc[2][2]); acc[2][3] = fma2(a2, whi.y, acc[2][3]);
            acc[3][0] = fma2(a3, wlo.x, acc[3][0]); acc[3][1] = fma2(a3, wlo.y, acc[3][1]);
            acc[3][2] = fma2(a3, whi.x, acc[3][2]); acc[3][3] = fma2(a3, whi.y, acc[3][3]);
        }
        __syncthreads();

        // ---- store partials: red[w][row][col] at w*16*RED_STR + row*RED_STR + col ----
        float* red = sAux;
#pragma unroll
        for (int j = 0; j < 4; j++) {
            int row = rg * 4 + j;
            float* dst = &red[w * (16 * RED_STR) + row * RED_STR];
            *(ull*)&dst[cg * 4]          = acc[j][0];
            *(ull*)&dst[cg * 4 + 2]      = acc[j][1];
            *(ull*)&dst[32 + cg * 4]     = acc[j][2];
            *(ull*)&dst[32 + cg * 4 + 2] = acc[j][3];
        }
        __syncthreads();

        // ---- reduce 8 partials, add xp, tanh, store h_t ----
        {
            float2 s0 = make_float2(0.f, 0.f), s1 = make_float2(0.f, 0.f);
            int rbase = ty * RED_STR + tx * 4;
#pragma unroll
            for (int w2 = 0; w2 < 8; w2++) {
                float2 u0 = unpack2(*(const ull*)&red[w2 * (16 * RED_STR) + rbase]);
                float2 u1 = unpack2(*(const ull*)&red[w2 * (16 * RED_STR) + rbase + 2]);
                s0.x += u0.x; s0.y += u0.y; s1.x += u1.x; s1.y += u1.y;
            }
            size_t base = (((size_t)(b0 + ty) * Tt) + t) * Hh + n0 + tx * 4;
            float4 xv = *(const float4*)&xp[base];
            float4 o;
            o.x = tanhf(s0.x + xv.x); o.y = tanhf(s0.y + xv.y);
            o.z = tanhf(s1.x + xv.z); o.w = tanhf(s1.y + xv.w);
            *(float4*)&h[base] = o;
        }
        __threadfence();
        __syncthreads();
        if (tid == 0 && t < Tt - 1) atomicAdd(cnt, 1);
    }
}

// ---------------------------------------------------------------------------
// Final: out[b] = h[b, T-1, :] @ Wf + bf
// ---------------------------------------------------------------------------
__global__ void final_kernel(const float* __restrict__ h, const float* __restrict__ Wf,
                             const float* __restrict__ bf, float* __restrict__ out)
{
    int b = blockIdx.x;
    const float* row = h + ((size_t)b * Tt + (Tt - 1)) * Hh;
    float s = 0.f;
    for (int j = threadIdx.x; j < Hh; j += 128) s += row[j] * Wf[j];
#pragma unroll
    for (int o = 16; o > 0; o >>= 1) s += __shfl_down_sync(0xffffffffu, s, o);
    __shared__ float ws[4];
    if ((threadIdx.x & 31) == 0) ws[threadIdx.x >> 5] = s;
    __syncthreads();
    if (threadIdx.x == 0) out[b] = ws[0] + ws[1] + ws[2] + ws[3] + bf[0];
}

// ---------------------------------------------------------------------------
extern "C" void kernel_launch(void* const* d_in, const int* in_sizes, int n_in,
                              void* d_out, int out_size)
{
    const float* x   = (const float*)d_in[0];
    const float* Wx0 = (const float*)d_in[1];
    const float* Wh0 = (const float*)d_in[2];
    const float* b0  = (const float*)d_in[3];
    const float* Wx1 = (const float*)d_in[4];
    const float* Wh1 = (const float*)d_in[5];
    const float* b1  = (const float*)d_in[6];
    const float* Wx2 = (const float*)d_in[7];
    const float* Wh2 = (const float*)d_in[8];
    const float* b2  = (const float*)d_in[9];
    const float* Wf  = (const float*)d_in[10];
    const float* bf  = (const float*)d_in[11];
    float* out = (float*)d_out;

    void* p;
    cudaGetSymbolAddress(&p, g_xp);
    float* xp = (float*)p;
    cudaGetSymbolAddress(&p, g_h);
    float* hb = (float*)p;
    cudaGetSymbolAddress(&p, g_bar);
    int* bar = (int*)p;

    cudaFuncSetAttribute(layer_kernel, cudaFuncAttributeMaxDynamicSharedMemorySize, LAYER_SMEM);

    dim3 pgrid(Hh / 64, (Bb * Tt) / 64);   // (8, 1024)
    dim3 lgrid(Hh / 64, Bb / 16);          // (8, 16) = 128 CTAs, all resident

    zero_bar_kernel<<<1, 64>>>();

    proj_kernel<Dd><<<pgrid, 256>>>(x, Wx0, b0, xp);
    layer_kernel<<<lgrid, 256, LAYER_SMEM>>>(xp, Wh0, hb, bar, 0);

    proj_kernel<Hh><<<pgrid, 256>>>(hb, Wx1, b1, xp);
    layer_kernel<<<lgrid, 256, LAYER_SMEM>>>(xp, Wh1, hb, bar, 1);

    proj_kernel<Hh><<<pgrid, 256>>>(hb, Wx2, b2, xp);
    layer_kernel<<<lgrid, 256, LAYER_SMEM>>>(xp, Wh2, hb, bar, 2);

    final_kernel<<<Bb, 128>>>(hb, Wf, bf, out);
}